// round 2
// baseline (speedup 1.0000x reference)
#include <cuda_runtime.h>

// GenSP superpixel affinity — GB300 sm_103a
// Shapes fixed by problem: B=4, C=64, H=W=256, stoken=16
#define BB    4
#define CC    64
#define HH    256
#define WW    256
#define NHB   16            // nH = nW = 16
#define NS    256           // superpixels per batch
#define PP    65536         // pixels per batch (H*W)
#define FSTR  257           // padded smem stride (conflict-free transposed reads)

// ---------------- device scratch (no runtime allocation allowed) ------------
__device__ float g_cent[BB * NS * CC];   // centroids  [b][s][c]
__device__ float g_num [BB * NS * CC];   // numerator  [b][s][c]
__device__ float g_den [BB * NS];        // denominator[b][s]
__device__ float g_aff [BB * 9 * PP];    // iter-1 affinities, layout [b][k][p]

// ---------------- K1: initial centroids (block means) + zero num/den --------
__global__ __launch_bounds__(256) void k_cent0(const float* __restrict__ x) {
    int blk = blockIdx.x;              // b*256 + s
    int b = blk >> 8, s = blk & 255;
    int si = s >> 4, sj = s & 15;
    int t = threadIdx.x, w = t >> 5, lane = t & 31;

    if (t < CC)  g_num[blk * CC + t] = 0.f;
    if (t == CC) g_den[blk] = 0.f;

    const float* xb = x + (size_t)b * CC * PP + (size_t)(si * 16) * WW + sj * 16;
    // warp w handles channels [8w, 8w+8)
    for (int cc = 0; cc < 8; cc++) {
        int c = w * 8 + cc;
        const float* xc = xb + (size_t)c * PP;
        float sum = 0.f;
        #pragma unroll
        for (int q = 0; q < 8; q++) {
            int pl = lane + q * 32;                 // local pixel 0..255
            sum += xc[(pl >> 4) * WW + (pl & 15)];
        }
        #pragma unroll
        for (int o = 16; o; o >>= 1) sum += __shfl_xor_sync(0xffffffffu, sum, o);
        if (lane == 0) g_cent[blk * CC + c] = sum * (1.f / 256.f);
    }
}

// ---------------- K2: affinity iter0 + num/den accumulation -----------------
// dyn smem layout: feats[64*FSTR] | cent[9*64] | c2[16] | aff[9*256]
#define SM2_BYTES ((CC * FSTR + 9 * CC + 16 + 9 * 256) * 4)

__global__ __launch_bounds__(256) void k_iter0(const float* __restrict__ x) {
    extern __shared__ float sm[];
    float* feats_s = sm;
    float* cent_s  = feats_s + CC * FSTR;
    float* c2_s    = cent_s + 9 * CC;
    float* aff_s   = c2_s + 16;

    int blk = blockIdx.x;                       // b*256 + tile
    int b = blk >> 8, bi = (blk >> 4) & 15, bj = blk & 15;
    int t = threadIdx.x;

    // candidate centroids into smem (invalid -> 0)
    for (int u = t; u < 9 * CC; u += 256) {
        int k = u >> 6, c = u & 63;
        int si = bi + (k / 3) - 1, sj = bj + (k % 3) - 1;
        float v = 0.f;
        if (si >= 0 && si < NHB && sj >= 0 && sj < NHB)
            v = g_cent[(((b << 8) + (si << 4) + sj) << 6) + c];
        cent_s[u] = v;
    }
    __syncthreads();
    if (t < 9) {
        float s2 = 0.f;
        for (int c = 0; c < CC; c++) { float v = cent_s[t * CC + c]; s2 += v * v; }
        c2_s[t] = s2;
    }

    // load this thread's pixel features (regs) + stage transposed in smem
    int li = t >> 4, lj = t & 15;
    const float* xp = x + (size_t)b * CC * PP + (size_t)(bi * 16 + li) * WW + (bj * 16 + lj);
    float f[CC]; float f2 = 0.f;
    #pragma unroll
    for (int c = 0; c < CC; c++) {
        float v = xp[(size_t)c * PP];
        f[c] = v; f2 += v * v;
        feats_s[c * FSTR + t] = v;
    }
    __syncthreads();

    // 9 restricted dot products (cent reads are warp-uniform broadcasts)
    float dot[9];
    #pragma unroll
    for (int k = 0; k < 9; k++) dot[k] = 0.f;
    #pragma unroll
    for (int c = 0; c < CC; c++) {
        float fc = f[c];
        #pragma unroll
        for (int k = 0; k < 9; k++) dot[k] += fc * cent_s[k * CC + c];
    }

    // masked softmax over 9 candidates
    float logit[9]; float m = -1e30f;
    #pragma unroll
    for (int k = 0; k < 9; k++) {
        int si = bi + (k / 3) - 1, sj = bj + (k % 3) - 1;
        bool valid = (si >= 0 && si < NHB && sj >= 0 && sj < NHB);
        float l = valid ? -(f2 + c2_s[k] - 2.f * dot[k]) : -1e30f;
        logit[k] = l; m = fmaxf(m, l);
    }
    float esum = 0.f, e[9];
    #pragma unroll
    for (int k = 0; k < 9; k++) {
        float ev = (logit[k] > -1e29f) ? __expf(logit[k] - m) : 0.f;
        e[k] = ev; esum += ev;
    }
    float inv = 1.f / esum;
    #pragma unroll
    for (int k = 0; k < 9; k++) aff_s[k * 256 + t] = e[k] * inv;
    __syncthreads();

    // num/den: num[k][c] = sum_p aff[k][p] * f[c][p]   (transposed smem reads)
    int c = t & 63, g = t >> 6;                 // 4 pixel-groups of 64
    float acc[9], dacc[9];
    #pragma unroll
    for (int k = 0; k < 9; k++) { acc[k] = 0.f; dacc[k] = 0.f; }
    const bool do_den = (c == 0);
    for (int pi = 0; pi < 64; pi++) {
        int p = (g << 6) + pi;
        float fv = feats_s[c * FSTR + p];       // conflict-free (stride 257)
        #pragma unroll
        for (int k = 0; k < 9; k++) {
            float a = aff_s[k * 256 + p];       // warp-uniform broadcast
            acc[k] += a * fv;
            if (do_den) dacc[k] += a;
        }
    }
    #pragma unroll
    for (int k = 0; k < 9; k++) {
        int si = bi + (k / 3) - 1, sj = bj + (k % 3) - 1;
        if (si >= 0 && si < NHB && sj >= 0 && sj < NHB) {
            int sidx = (b << 8) + (si << 4) + sj;
            atomicAdd(&g_num[(sidx << 6) + c], acc[k]);
            if (do_den) atomicAdd(&g_den[sidx], dacc[k]);
        }
    }
}

// ---------------- K3: centroid update ---------------------------------------
__global__ __launch_bounds__(256) void k_centup() {
    int e = blockIdx.x * 256 + threadIdx.x;     // 65536 elems
    g_cent[e] = g_num[e] / (g_den[e >> 6] + 1e-16f);
}

// ---------------- K4: affinity iter1 -> g_aff (B,9,P) -----------------------
__global__ __launch_bounds__(256) void k_iter1(const float* __restrict__ x) {
    __shared__ float cent_s[9 * CC];
    __shared__ float c2_s[16];

    int blk = blockIdx.x;
    int b = blk >> 8, bi = (blk >> 4) & 15, bj = blk & 15;
    int t = threadIdx.x;

    for (int u = t; u < 9 * CC; u += 256) {
        int k = u >> 6, c = u & 63;
        int si = bi + (k / 3) - 1, sj = bj + (k % 3) - 1;
        float v = 0.f;
        if (si >= 0 && si < NHB && sj >= 0 && sj < NHB)
            v = g_cent[(((b << 8) + (si << 4) + sj) << 6) + c];
        cent_s[u] = v;
    }
    __syncthreads();
    if (t < 9) {
        float s2 = 0.f;
        for (int c = 0; c < CC; c++) { float v = cent_s[t * CC + c]; s2 += v * v; }
        c2_s[t] = s2;
    }

    int li = t >> 4, lj = t & 15;
    const float* xp = x + (size_t)b * CC * PP + (size_t)(bi * 16 + li) * WW + (bj * 16 + lj);
    float f[CC]; float f2 = 0.f;
    #pragma unroll
    for (int c = 0; c < CC; c++) { float v = xp[(size_t)c * PP]; f[c] = v; f2 += v * v; }
    __syncthreads();

    float dot[9];
    #pragma unroll
    for (int k = 0; k < 9; k++) dot[k] = 0.f;
    #pragma unroll
    for (int c = 0; c < CC; c++) {
        float fc = f[c];
        #pragma unroll
        for (int k = 0; k < 9; k++) dot[k] += fc * cent_s[k * CC + c];
    }

    float logit[9]; float m = -1e30f;
    #pragma unroll
    for (int k = 0; k < 9; k++) {
        int si = bi + (k / 3) - 1, sj = bj + (k % 3) - 1;
        bool valid = (si >= 0 && si < NHB && sj >= 0 && sj < NHB);
        float l = valid ? -(f2 + c2_s[k] - 2.f * dot[k]) : -1e30f;
        logit[k] = l; m = fmaxf(m, l);
    }
    float esum = 0.f, e[9];
    #pragma unroll
    for (int k = 0; k < 9; k++) {
        float ev = (logit[k] > -1e29f) ? __expf(logit[k] - m) : 0.f;
        e[k] = ev; esum += ev;
    }
    float inv = 1.f / esum;

    int pg = (bi * 16 + li) * WW + (bj * 16 + lj);
    #pragma unroll
    for (int k = 0; k < 9; k++)
        g_aff[((b * 9 + k) << 16) + pg] = e[k] * inv;
}

// ---------------- K5: dense scatter to output (B,nS,P) ----------------------
__global__ __launch_bounds__(256) void k_scatter(float* __restrict__ out) {
    int row = blockIdx.y;                       // b*256 + s
    int b = row >> 8, s = row & 255;
    int si = s >> 4, sj = s & 15;
    int idx = blockIdx.x * 256 + threadIdx.x;   // float4 index in [0,16384)
    int p = idx << 2;
    int i = p >> 8, j = p & 255;
    int di = si - (i >> 4), dj = sj - (j >> 4);

    float4 v = make_float4(0.f, 0.f, 0.f, 0.f);
    if (di >= -1 && di <= 1 && dj >= -1 && dj <= 1) {
        int k = (di + 1) * 3 + (dj + 1);
        v = *reinterpret_cast<const float4*>(&g_aff[((size_t)(b * 9 + k) << 16) + p]);
    }
    *reinterpret_cast<float4*>(&out[((size_t)row << 16) + p]) = v;
}

// ---------------- launch -----------------------------------------------------
extern "C" void kernel_launch(void* const* d_in, const int* in_sizes, int n_in,
                              void* d_out, int out_size) {
    const float* x = (const float*)d_in[0];     // (4,64,256,256) fp32
    float* out = (float*)d_out;                 // (4,256,65536) fp32

    cudaFuncSetAttribute(k_iter0, cudaFuncAttributeMaxDynamicSharedMemorySize, SM2_BYTES);

    k_cent0 <<<BB * NS, 256>>>(x);
    k_iter0 <<<BB * NS, 256, SM2_BYTES>>>(x);
    k_centup<<<(BB * NS * CC) / 256, 256>>>();
    k_iter1 <<<BB * NS, 256>>>(x);
    dim3 g5(PP / 4 / 256, BB * NS);
    k_scatter<<<g5, 256>>>(out);
}